// round 15
// baseline (speedup 1.0000x reference)
#include <cuda_runtime.h>
#include <cuda_fp16.h>
#include <cstdint>

// ===========================================================================
// TransConvLayer reduction (validated R4/R6-R14):
//   out[n,:] = source[n,:] @ Wbar^T + bbar
// Round 15: fp16 single-term pipelined GEMM (R14) at 3 CTAs/SM.
//   Chunk staging split into two half-waves -> pend 4 float4 (16 regs),
//   total ~82 regs, fits __launch_bounds__(256,3) (85-reg cap).
//   smem 65.8 KB x 3 = 197 KB < 228 KB. More resident CTAs = more
//   outstanding LDG streams = higher DRAM duty.
// ===========================================================================

#define IN_CH   256
#define OUT_CH  64
#define TILE_M  128
#define THREADS 256            // 8 warps: 4 row-groups x 2 col-groups
#define KCH     64             // K per chunk
#define NCH     4              // chunks

// SMEM layout (bytes from 1024-aligned base).
//   W: 64 rows x 512 B (full K=256 fp16), swizzled        -> 32 KB
//   X: 2 stages x [128 rows x 128 B] (K=64 fp16 chunk)    -> 32 KB
#define OFF_W    0
#define OFF_XB   32768
#define XSTAGE   16384
#define OFF_BIAS 65536         // 64 floats
#define SMEM_SZ  65792
#define SMEM_DYN (SMEM_SZ + 1024)

// ---- device weight globals (prep kernel fills) -------------------------------
__device__ __half g_Wh[OUT_CH * IN_CH];   // [d][k] row-major, folded mean
__device__ float  g_b[OUT_CH];

__global__ void prep_kernel(const float* __restrict__ Wv_w,
                            const float* __restrict__ Wv_b) {
    int idx = blockIdx.x * blockDim.x + threadIdx.x;   // 0..16383
    if (idx < OUT_CH * IN_CH) {
        int d = idx >> 8;
        int k = idx & 255;
        float s = 0.f;
        #pragma unroll
        for (int h = 0; h < 4; ++h) s += Wv_w[(h * OUT_CH + d) * IN_CH + k];
        g_Wh[idx] = __float2half_rn(0.25f * s);
    }
    if (idx < OUT_CH) {
        float s = 0.f;
        #pragma unroll
        for (int h = 0; h < 4; ++h) s += Wv_b[h * OUT_CH + idx];
        g_b[idx] = 0.25f * s;
    }
}

// ---- helpers ----------------------------------------------------------------

__device__ __forceinline__ uint32_t smem_u32(const void* p) {
    uint32_t a;
    asm("{ .reg .u64 t; cvta.to.shared.u64 t, %1; cvt.u32.u64 %0, t; }"
        : "=r"(a) : "l"(p));
    return a;
}

__device__ __forceinline__ void ldsm_x4(uint32_t* r, uint32_t addr) {
    asm volatile("ldmatrix.sync.aligned.m8n8.x4.shared.b16 {%0,%1,%2,%3}, [%4];"
                 : "=r"(r[0]), "=r"(r[1]), "=r"(r[2]), "=r"(r[3]) : "r"(addr));
}

__device__ __forceinline__ void mma_16816(float* c, const uint32_t* a,
                                          const uint32_t* b) {
    asm volatile(
        "mma.sync.aligned.m16n8k16.row.col.f32.f16.f16.f32 "
        "{%0,%1,%2,%3}, {%4,%5,%6,%7}, {%8,%9}, {%0,%1,%2,%3};"
        : "+f"(c[0]), "+f"(c[1]), "+f"(c[2]), "+f"(c[3])
        : "r"(a[0]), "r"(a[1]), "r"(a[2]), "r"(a[3]), "r"(b[0]), "r"(b[1]));
}

__device__ __forceinline__ uint32_t f22h(float x, float y) {
    __half2 h = __floats2half2_rn(x, y);
    return *reinterpret_cast<const uint32_t*>(&h);
}

// ---- main kernel --------------------------------------------------------------

__global__ __launch_bounds__(THREADS, 3)
void gemm_kernel(const float* __restrict__ X, float* __restrict__ Y, int N) {
    extern __shared__ char smem_raw[];
    uint32_t raw  = smem_u32(smem_raw);
    uint32_t base = (raw + 1023) & ~1023u;
    char*    sm   = smem_raw + (base - raw);

    const int tid  = threadIdx.x;
    const int wid  = tid >> 5;
    const int lid  = tid & 31;
    const int wr   = wid >> 1;            // 0..3  -> rows wr*32
    const int wc   = wid & 1;             // 0..1  -> cols wc*32
    const int row0 = blockIdx.x * TILE_M;

    // ---- stage W (fp16, folded by prep): 64 rows x 32 chunks, swizzled ----
    #pragma unroll
    for (int it = 0; it < 8; ++it) {
        int idx = it * THREADS + tid;     // 0..2047
        int r   = idx >> 5;               // 0..63
        int c   = idx & 31;               // 16B chunk = 8 fp16
        uint32_t off = (uint32_t)(r * 512 + ((c ^ (r & 7)) << 4));
        *reinterpret_cast<uint4*>(sm + OFF_W + off) =
            *reinterpret_cast<const uint4*>(g_Wh + r * IN_CH + c * 8);
    }
    if (tid < OUT_CH)
        *reinterpret_cast<float*>(sm + OFF_BIAS + tid * 4) = g_b[tid];

    // ---- half-chunk staging helpers (pend = 4 float4 = 16 regs) ----
    // half h of chunk kc = 128 rows x 32 k fp32; fp16 chunk cols h*4..h*4+3
    auto load_half = [&](float4* pend, int kc, int h) {
        const int kc0 = kc * KCH + h * 32;
        #pragma unroll
        for (int it = 0; it < 2; ++it) {
            int idx = it * THREADS + tid;   // 0..511
            int r   = idx >> 2;             // 0..127
            int c   = idx & 3;              // 32B fp32 group (8 k values)
            int gr  = row0 + r;
            if (gr >= N) gr = N - 1;        // clamp; epilogue guards rows
            const float4* gp = reinterpret_cast<const float4*>(
                X + (size_t)gr * IN_CH + kc0 + c * 8);
            pend[2 * it]     = gp[0];
            pend[2 * it + 1] = gp[1];
        }
    };
    auto cvt_sts_half = [&](const float4* pend, int st, int h) {
        char* dst = sm + OFF_XB + st * XSTAGE;
        #pragma unroll
        for (int it = 0; it < 2; ++it) {
            int idx = it * THREADS + tid;
            int r   = idx >> 2;
            int cc  = h * 4 + (idx & 3);    // 16B fp16 chunk col 0..7
            float4 a = pend[2 * it];
            float4 b = pend[2 * it + 1];
            uint4 hh;
            hh.x = f22h(a.x, a.y);
            hh.y = f22h(a.z, a.w);
            hh.z = f22h(b.x, b.y);
            hh.w = f22h(b.z, b.w);
            uint32_t off = (uint32_t)(r * 128 + ((cc ^ (r & 7)) << 4));
            *reinterpret_cast<uint4*>(dst + off) = hh;
        }
    };

    // ---- prologue: stage chunk 0 (both halves) ----
    {
        float4 pend[4];
        load_half(pend, 0, 0);
        cvt_sts_half(pend, 0, 0);
        load_half(pend, 0, 1);
        cvt_sts_half(pend, 0, 1);
    }
    __syncthreads();

    // ---- per-lane ldmatrix address components ----
    // A: chunk layout, row stride 128 B (chunks 0..7)
    const int rA    = wr * 32 + ((lid >> 3) & 1) * 8 + (lid & 7);
    const int chA   = lid >> 4;
    const int swzA  = rA & 7;
    const uint32_t aRow0 = (uint32_t)(rA * 128);
    const uint32_t aRow1 = (uint32_t)((rA + 16) * 128);
    // B: full-K layout, row stride 512 B (chunks 0..31)
    const int rBb   = wc * 32 + ((lid >> 4) & 1) * 8 + (lid & 7);
    const int chB   = (lid >> 3) & 1;
    const int swzB  = rBb & 7;
    const uint32_t bRow0 = (uint32_t)(rBb * 512);
    const uint32_t bRow1 = (uint32_t)((rBb + 16) * 512);

    const uint32_t wsm = base + OFF_W;

    float acc[2][4][4];
    #pragma unroll
    for (int mt = 0; mt < 2; ++mt)
        #pragma unroll
        for (int nt = 0; nt < 4; ++nt)
            #pragma unroll
            for (int q = 0; q < 4; ++q) acc[mt][nt][q] = 0.f;

    // ---- pipelined chunk loop (half-wave staging between MMA groups) ----
    #pragma unroll
    for (int kc = 0; kc < NCH; ++kc) {
        const uint32_t xsm = base + OFF_XB + (uint32_t)(kc & 1) * XSTAGE;
        const int st_nx = (kc + 1) & 1;
        float4 pend[4];

        if (kc < NCH - 1) load_half(pend, kc + 1, 0);

        #pragma unroll
        for (int ks = 0; ks < 4; ++ks) {
            const int ksg = kc * 4 + ks;
            const uint32_t oA = (uint32_t)(((2 * ks  + chA) ^ swzA) << 4);
            const uint32_t oB = (uint32_t)(((2 * ksg + chB) ^ swzB) << 4);

            uint32_t ah0[4], ah1[4], bh[8];
            ldsm_x4(ah0, xsm + aRow0 + oA);
            ldsm_x4(ah1, xsm + aRow1 + oA);
            ldsm_x4(bh,     wsm + bRow0 + oB);
            ldsm_x4(bh + 4, wsm + bRow1 + oB);

            #pragma unroll
            for (int nt = 0; nt < 4; ++nt) {
                mma_16816(acc[0][nt], ah0, bh + 2 * nt);
                mma_16816(acc[1][nt], ah1, bh + 2 * nt);
            }

            // after the first half of the MMA, rotate staging waves
            if (ks == 1 && kc < NCH - 1) {
                cvt_sts_half(pend, st_nx, 0);
                load_half(pend, kc + 1, 1);
            }
        }

        if (kc < NCH - 1) cvt_sts_half(pend, st_nx, 1);
        __syncthreads();
    }

    // ---- epilogue: D frag -> global, + bias (from smem) ----
    const int qr = lid >> 2;               // 0..7
    const int qc = (lid & 3) * 2;
    const float* bias = reinterpret_cast<const float*>(sm + OFF_BIAS);
    #pragma unroll
    for (int mt = 0; mt < 2; ++mt) {
        int r_lo = row0 + wr * 32 + mt * 16 + qr;
        #pragma unroll
        for (int nt = 0; nt < 4; ++nt) {
            int col = wc * 32 + nt * 8 + qc;
            float b0 = bias[col], b1 = bias[col + 1];
            if (r_lo < N) {
                float2 v = make_float2(acc[mt][nt][0] + b0,
                                       acc[mt][nt][1] + b1);
                *reinterpret_cast<float2*>(Y + (size_t)r_lo * OUT_CH + col) = v;
            }
            if (r_lo + 8 < N) {
                float2 v = make_float2(acc[mt][nt][2] + b0,
                                       acc[mt][nt][3] + b1);
                *reinterpret_cast<float2*>(Y + (size_t)(r_lo + 8) * OUT_CH + col) = v;
            }
        }
    }
}

// ---------------------------------------------------------------------------

extern "C" void kernel_launch(void* const* d_in, const int* in_sizes, int n_in,
                              void* d_out, int out_size) {
    // inputs: query_input, source_input, Wq_w, Wq_b, Wk_w, Wk_b, Wv_w, Wv_b
    const float* src  = (const float*)d_in[1];
    const float* Wv_w = (const float*)d_in[6];
    const float* Wv_b = (const float*)d_in[7];
    float* out = (float*)d_out;
    const int N = in_sizes[1] / IN_CH;

    cudaFuncSetAttribute(gemm_kernel,
                         cudaFuncAttributeMaxDynamicSharedMemorySize, SMEM_DYN);

    prep_kernel<<<64, 256>>>(Wv_w, Wv_b);
    const int grid = (N + TILE_M - 1) / TILE_M;   // 782
    gemm_kernel<<<grid, THREADS, SMEM_DYN>>>(src, out, N);
}

// round 16
// speedup vs baseline: 1.3340x; 1.3340x over previous
#include <cuda_runtime.h>
#include <cuda_fp16.h>
#include <cstdint>

// ===========================================================================
// TransConvLayer reduction (validated R4/R6-R15):
//   out[n,:] = source[n,:] @ Wbar^T + bbar
// Round 16: R14 (best, 33.3 us) + prologue reorder only.
//   Chunk-0's DRAM LDGs are issued FIRST; W staging (L2-hot) executes under
//   that latency instead of ahead of it. Everything else is bit-identical
//   to R14: fp16 single-term HMMA, K in 4 chunks of 64, double-buffered X,
//   W resident, 2 CTAs/SM, pend=8 LDG.128/thread (the measured MLP optimum;
//   R15 proved 3 CTAs with pend=4 loses).
// ===========================================================================

#define IN_CH   256
#define OUT_CH  64
#define TILE_M  128
#define THREADS 256            // 8 warps: 4 row-groups x 2 col-groups
#define KCH     64             // K per chunk
#define NCH     4              // chunks

// SMEM layout (bytes from 1024-aligned base).
//   W: 64 rows x 512 B (full K=256 fp16), swizzled        -> 32 KB
//   X: 2 stages x [128 rows x 128 B] (K=64 fp16 chunk)    -> 32 KB
#define OFF_W    0
#define OFF_XB   32768
#define XSTAGE   16384
#define OFF_BIAS 65536         // 64 floats
#define SMEM_SZ  65792
#define SMEM_DYN (SMEM_SZ + 1024)

// ---- device weight globals (prep kernel fills) -------------------------------
__device__ __half g_Wh[OUT_CH * IN_CH];   // [d][k] row-major, folded mean
__device__ float  g_b[OUT_CH];

__global__ void prep_kernel(const float* __restrict__ Wv_w,
                            const float* __restrict__ Wv_b) {
    int idx = blockIdx.x * blockDim.x + threadIdx.x;   // 0..16383
    if (idx < OUT_CH * IN_CH) {
        int d = idx >> 8;
        int k = idx & 255;
        float s = 0.f;
        #pragma unroll
        for (int h = 0; h < 4; ++h) s += Wv_w[(h * OUT_CH + d) * IN_CH + k];
        g_Wh[idx] = __float2half_rn(0.25f * s);
    }
    if (idx < OUT_CH) {
        float s = 0.f;
        #pragma unroll
        for (int h = 0; h < 4; ++h) s += Wv_b[h * OUT_CH + idx];
        g_b[idx] = 0.25f * s;
    }
}

// ---- helpers ----------------------------------------------------------------

__device__ __forceinline__ uint32_t smem_u32(const void* p) {
    uint32_t a;
    asm("{ .reg .u64 t; cvta.to.shared.u64 t, %1; cvt.u32.u64 %0, t; }"
        : "=r"(a) : "l"(p));
    return a;
}

__device__ __forceinline__ void ldsm_x4(uint32_t* r, uint32_t addr) {
    asm volatile("ldmatrix.sync.aligned.m8n8.x4.shared.b16 {%0,%1,%2,%3}, [%4];"
                 : "=r"(r[0]), "=r"(r[1]), "=r"(r[2]), "=r"(r[3]) : "r"(addr));
}

__device__ __forceinline__ void mma_16816(float* c, const uint32_t* a,
                                          const uint32_t* b) {
    asm volatile(
        "mma.sync.aligned.m16n8k16.row.col.f32.f16.f16.f32 "
        "{%0,%1,%2,%3}, {%4,%5,%6,%7}, {%8,%9}, {%0,%1,%2,%3};"
        : "+f"(c[0]), "+f"(c[1]), "+f"(c[2]), "+f"(c[3])
        : "r"(a[0]), "r"(a[1]), "r"(a[2]), "r"(a[3]), "r"(b[0]), "r"(b[1]));
}

__device__ __forceinline__ uint32_t f22h(float x, float y) {
    __half2 h = __floats2half2_rn(x, y);
    return *reinterpret_cast<const uint32_t*>(&h);
}

// ---- main kernel --------------------------------------------------------------

__global__ __launch_bounds__(THREADS, 2)
void gemm_kernel(const float* __restrict__ X, float* __restrict__ Y, int N) {
    extern __shared__ char smem_raw[];
    uint32_t raw  = smem_u32(smem_raw);
    uint32_t base = (raw + 1023) & ~1023u;
    char*    sm   = smem_raw + (base - raw);

    const int tid  = threadIdx.x;
    const int wid  = tid >> 5;
    const int lid  = tid & 31;
    const int wr   = wid >> 1;            // 0..3  -> rows wr*32
    const int wc   = wid & 1;             // 0..1  -> cols wc*32
    const int row0 = blockIdx.x * TILE_M;

    // ---- chunk staging helpers ----
    // chunk = 128 rows x 64 k fp32 -> fp16 [128 rows x 128 B], swz c^(r&7)
    auto load_chunk = [&](float4* pend, int kc) {
        const int kc0 = kc * KCH;
        #pragma unroll
        for (int it = 0; it < 4; ++it) {
            int idx = it * THREADS + tid;   // 0..1023
            int r   = idx >> 3;             // 0..127
            int c   = idx & 7;              // 16B fp16 chunk = 8 k values
            int gr  = row0 + r;
            if (gr >= N) gr = N - 1;        // clamp; epilogue guards rows
            const float4* gp = reinterpret_cast<const float4*>(
                X + (size_t)gr * IN_CH + kc0 + c * 8);
            pend[2 * it]     = gp[0];
            pend[2 * it + 1] = gp[1];
        }
    };
    auto cvt_sts_chunk = [&](const float4* pend, int st) {
        char* dst = sm + OFF_XB + st * XSTAGE;
        #pragma unroll
        for (int it = 0; it < 4; ++it) {
            int idx = it * THREADS + tid;
            int r   = idx >> 3;
            int c   = idx & 7;
            float4 a = pend[2 * it];
            float4 b = pend[2 * it + 1];
            uint4 h;
            h.x = f22h(a.x, a.y);
            h.y = f22h(a.z, a.w);
            h.z = f22h(b.x, b.y);
            h.w = f22h(b.z, b.w);
            uint32_t off = (uint32_t)(r * 128 + ((c ^ (r & 7)) << 4));
            *reinterpret_cast<uint4*>(dst + off) = h;
        }
    };

    // ---- prologue: issue chunk-0 DRAM loads FIRST, then stage W (L2-hot)
    //      under that latency, then convert chunk 0. ----
    {
        float4 pend[8];
        load_chunk(pend, 0);                 // DRAM LDGs in flight

        // stage W (fp16, folded by prep): 64 rows x 32 chunks, swizzled
        #pragma unroll
        for (int it = 0; it < 8; ++it) {
            int idx = it * THREADS + tid;    // 0..2047
            int r   = idx >> 5;              // 0..63
            int c   = idx & 31;              // 16B chunk = 8 fp16
            uint32_t off = (uint32_t)(r * 512 + ((c ^ (r & 7)) << 4));
            *reinterpret_cast<uint4*>(sm + OFF_W + off) =
                *reinterpret_cast<const uint4*>(g_Wh + r * IN_CH + c * 8);
        }
        if (tid < OUT_CH)
            *reinterpret_cast<float*>(sm + OFF_BIAS + tid * 4) = g_b[tid];

        cvt_sts_chunk(pend, 0);              // consumes the DRAM loads
    }
    __syncthreads();

    // ---- per-lane ldmatrix address components ----
    // A: chunk layout, row stride 128 B (chunks 0..7)
    const int rA    = wr * 32 + ((lid >> 3) & 1) * 8 + (lid & 7);
    const int chA   = lid >> 4;
    const int swzA  = rA & 7;
    const uint32_t aRow0 = (uint32_t)(rA * 128);
    const uint32_t aRow1 = (uint32_t)((rA + 16) * 128);
    // B: full-K layout, row stride 512 B (chunks 0..31)
    const int rBb   = wc * 32 + ((lid >> 4) & 1) * 8 + (lid & 7);
    const int chB   = (lid >> 3) & 1;
    const int swzB  = rBb & 7;
    const uint32_t bRow0 = (uint32_t)(rBb * 512);
    const uint32_t bRow1 = (uint32_t)((rBb + 16) * 512);

    const uint32_t wsm = base + OFF_W;

    float acc[2][4][4];
    #pragma unroll
    for (int mt = 0; mt < 2; ++mt)
        #pragma unroll
        for (int nt = 0; nt < 4; ++nt)
            #pragma unroll
            for (int q = 0; q < 4; ++q) acc[mt][nt][q] = 0.f;

    // ---- pipelined chunk loop (R14 structure, unchanged) ----
    #pragma unroll
    for (int kc = 0; kc < NCH; ++kc) {
        // issue next chunk's global loads BEFORE this chunk's MMA
        float4 pend[8];
        if (kc < NCH - 1) load_chunk(pend, kc + 1);

        const uint32_t xsm = base + OFF_XB + (uint32_t)(kc & 1) * XSTAGE;

        #pragma unroll
        for (int ks = 0; ks < 4; ++ks) {
            const int ksg = kc * 4 + ks;
            const uint32_t oA = (uint32_t)(((2 * ks  + chA) ^ swzA) << 4);
            const uint32_t oB = (uint32_t)(((2 * ksg + chB) ^ swzB) << 4);

            uint32_t ah0[4], ah1[4], bh[8];
            ldsm_x4(ah0, xsm + aRow0 + oA);
            ldsm_x4(ah1, xsm + aRow1 + oA);
            ldsm_x4(bh,     wsm + bRow0 + oB);
            ldsm_x4(bh + 4, wsm + bRow1 + oB);

            #pragma unroll
            for (int nt = 0; nt < 4; ++nt) {
                mma_16816(acc[0][nt], ah0, bh + 2 * nt);
                mma_16816(acc[1][nt], ah1, bh + 2 * nt);
            }
        }

        // convert + store next chunk into the other stage, then sync
        if (kc < NCH - 1) cvt_sts_chunk(pend, (kc + 1) & 1);
        __syncthreads();
    }

    // ---- epilogue: D frag -> global, + bias (from smem) ----
    const int qr = lid >> 2;               // 0..7
    const int qc = (lid & 3) * 2;
    const float* bias = reinterpret_cast<const float*>(sm + OFF_BIAS);
    #pragma unroll
    for (int mt = 0; mt < 2; ++mt) {
        int r_lo = row0 + wr * 32 + mt * 16 + qr;
        #pragma unroll
        for (int nt = 0; nt < 4; ++nt) {
            int col = wc * 32 + nt * 8 + qc;
            float b0 = bias[col], b1 = bias[col + 1];
            if (r_lo < N) {
                float2 v = make_float2(acc[mt][nt][0] + b0,
                                       acc[mt][nt][1] + b1);
                *reinterpret_cast<float2*>(Y + (size_t)r_lo * OUT_CH + col) = v;
            }
            if (r_lo + 8 < N) {
                float2 v = make_float2(acc[mt][nt][2] + b0,
                                       acc[mt][nt][3] + b1);
                *reinterpret_cast<float2*>(Y + (size_t)(r_lo + 8) * OUT_CH + col) = v;
            }
        }
    }
}

// ---------------------------------------------------------------------------

extern "C" void kernel_launch(void* const* d_in, const int* in_sizes, int n_in,
                              void* d_out, int out_size) {
    // inputs: query_input, source_input, Wq_w, Wq_b, Wk_w, Wk_b, Wv_w, Wv_b
    const float* src  = (const float*)d_in[1];
    const float* Wv_w = (const float*)d_in[6];
    const float* Wv_b = (const float*)d_in[7];
    float* out = (float*)d_out;
    const int N = in_sizes[1] / IN_CH;

    cudaFuncSetAttribute(gemm_kernel,
                         cudaFuncAttributeMaxDynamicSharedMemorySize, SMEM_DYN);

    prep_kernel<<<64, 256>>>(Wv_w, Wv_b);
    const int grid = (N + TILE_M - 1) / TILE_M;   // 782
    gemm_kernel<<<grid, THREADS, SMEM_DYN>>>(src, out, N);
}